// round 11
// baseline (speedup 1.0000x reference)
#include <cuda_runtime.h>
#include <math.h>

#define NB 128
#define DD 192
#define DEPTHL 12
#define NHD 3
#define HDIM 64
#define NE 4
#define NT 65
#define NCLS 100
#define DH 384
#define NTHR 768
#define NWARP 24
#define CK 40
#define OHS 68
#define PADQ 193
#define PADG 385
#define HALF 1158      // float4s per half-buffer: max(6*193, 3*385)
#define WBUF (2*HALF)

typedef unsigned long long ull;

struct __align__(16) SM {
    float t[66 * DD];
    float Y[72 * DD];
    float S[72 * DD];        // qkv per head; MoE: Hc (40x384) spills into Oh
    float Oh[72 * OHS];
    float4 Wsh4[WBUF];
    float m[72], rs[72];
    float gl[NT * NE];
    float selw[NT * 2];
    float ewt[NE * 80];
    int   seli[NT * 2];
    int   elist[NE * 80];
    int   ecnt[NE];
};

__device__ __forceinline__ ull fma2(ull a, ull b, ull c) {
    ull d;
    asm("fma.rn.f32x2 %0, %1, %2, %3;" : "=l"(d) : "l"(a), "l"(b), "l"(c));
    return d;
}
__device__ __forceinline__ float f2sum(ull v) {
    float lo = __uint_as_float((unsigned)(v & 0xffffffffull));
    float hi = __uint_as_float((unsigned)(v >> 32));
    return lo + hi;
}
__device__ __forceinline__ float gelu_exact(float x) {
    return 0.5f * x * (1.0f + erff(x * 0.70710678118654752f));
}
__device__ __forceinline__ float dot4(float4 a, float4 b) {
    return a.x * b.x + a.y * b.y + a.z * b.z + a.w * b.w;
}
__device__ __forceinline__ void cp_async16(void* dst, const void* src) {
    unsigned s = (unsigned)__cvta_generic_to_shared(dst);
    asm volatile("cp.async.cg.shared.global [%0], [%1], 16;" :: "r"(s), "l"(src) : "memory");
}
__device__ __forceinline__ void cp_commit() { asm volatile("cp.async.commit_group;" ::: "memory"); }
__device__ __forceinline__ void cp_wait_all() { asm volatile("cp.async.wait_group 0;" ::: "memory"); }

__device__ __forceinline__ void ln_stats(const float* __restrict__ base, int n0, int n1,
                                         float* __restrict__ m, float* __restrict__ rs) {
    int warp = threadIdx.x >> 5, lane = threadIdx.x & 31;
    for (int n = n0 + warp; n < n1; n += NWARP) {
        const float* row = base + n * DD;
        float s = 0.f;
        for (int c = lane; c < DD; c += 32) s += row[c];
#pragma unroll
        for (int o = 16; o; o >>= 1) s += __shfl_xor_sync(0xffffffffu, s, o);
        float mm = s * (1.0f / DD);
        float q = 0.f;
        for (int c = lane; c < DD; c += 32) { float d = row[c] - mm; q += d * d; }
#pragma unroll
        for (int o = 16; o; o >>= 1) q += __shfl_xor_sync(0xffffffffu, q, o);
        if (lane == 0) { m[n] = mm; rs[n] = rsqrtf(q * (1.0f / DD) + 1e-5f); }
    }
}

__global__ void __launch_bounds__(NTHR, 1) hypervit_kernel(
    const float* __restrict__ x, const float* __restrict__ conv_w, const float* __restrict__ conv_b,
    const float* __restrict__ pe_g, const float* __restrict__ pe_b,
    const float* __restrict__ cls_token, const float* __restrict__ pos_embed,
    const float* __restrict__ n1_g, const float* __restrict__ n1_b,
    const float* __restrict__ qkv_w, const float* __restrict__ temp,
    const float* __restrict__ proj_w, const float* __restrict__ proj_b,
    const float* __restrict__ n2_g, const float* __restrict__ n2_b,
    const float* __restrict__ gate_w, const float* __restrict__ gate_b,
    const float* __restrict__ e_w1, const float* __restrict__ e_b1,
    const float* __restrict__ e_w2, const float* __restrict__ e_b2,
    const float* __restrict__ attn_scale, const float* __restrict__ mlp_scale,
    const float* __restrict__ norm_g, const float* __restrict__ norm_b,
    const float* __restrict__ hc_w, const float* __restrict__ hc_b,
    const float* __restrict__ head_w, const float* __restrict__ head_b,
    float* __restrict__ out)
{
    extern __shared__ char smraw[];
    SM* sp = (SM*)smraw;
    const int b = blockIdx.x;
    const int tid = threadIdx.x;
    const int warp = tid >> 5, lane = tid & 31;
    float* t = sp->t;
    float* Y = sp->Y;
    float* S = sp->S;
    float* Oh = sp->Oh;
    float4* Wsh4 = sp->Wsh4;

    for (int i = tid; i < 6 * DD; i += NTHR) Y[66 * DD + i] = 0.f;

    // ======================= patch embed =======================
    {
        float* P = Y;
        for (int i = tid; i < 64 * 48; i += NTHR) {
            int patch = i / 48, f = i % 48;
            int c = f >> 4, pi = (f >> 2) & 3, pj = f & 3;
            int ph = patch >> 3, pw = patch & 7;
            P[i] = x[((b * 3 + c) * 32 + ph * 4 + pi) * 32 + pw * 4 + pj];
        }
        __syncthreads();
        for (int task = tid; task < 64 * DD; task += NTHR) {
            int p = task / DD, c = task % DD;
            const float* w = conv_w + c * 48;
            float acc = conv_b[c];
#pragma unroll
            for (int k = 0; k < 48; k += 4) {
                float4 w4 = *(const float4*)(w + k);
                float4 p4 = *(const float4*)(P + p * 48 + k);
                acc += dot4(p4, w4);
            }
            t[(p + 1) * DD + c] = acc;
        }
        __syncthreads();
        ln_stats(t, 1, 65, sp->m, sp->rs);
        __syncthreads();
        for (int i = tid; i < 64 * DD; i += NTHR) {
            int n = 1 + i / DD, c = i % DD;
            t[n * DD + c] = (t[n * DD + c] - sp->m[n]) * sp->rs[n] * pe_g[c] + pe_b[c]
                            + pos_embed[n * DD + c];
        }
        for (int c = tid; c < DD; c += NTHR) {
            t[c] = cls_token[c] + pos_embed[c];
            t[65 * DD + c] = 0.f;
        }
    }
    __syncthreads();

    // ======================= transformer layers =======================
    for (int l = 0; l < DEPTHL; l++) {
        // staging lambdas (double-buffered halves of Wsh4)
        auto issue_qkv = [&](int hh, int s) {
            float4* dst = Wsh4 + (s & 1) * HALF;
            int k40 = s * 6;
            for (int i = tid; i < 192 * 6; i += NTHR) {
                int col = i / 6, kk = i - col * 6;
                int sec = col >> 6, d = col & 63;
                const float* src = qkv_w + ((size_t)(l * 3 + sec) * DD + hh * HDIM + d) * DD
                                   + 4 * (k40 + kk);
                cp_async16(&dst[kk * PADQ + col], src);
            }
            cp_commit();
        };
        auto issue_proj = [&](int hh, int s) {
            float4* dst = Wsh4 + (s & 1) * HALF;
            int k40 = s * 4;
            for (int i = tid; i < 192 * 4; i += NTHR) {
                int col = i / 4, kk = i - col * 4;
                const float* src = proj_w + ((size_t)l * DD + col) * DD + hh * HDIM + 4 * (k40 + kk);
                cp_async16(&dst[kk * PADQ + col], src);
            }
            cp_commit();
        };

        // ---- LN1 -> Y ----
        ln_stats(t, 0, 65, sp->m, sp->rs);
        __syncthreads();
        for (int i = tid; i < 65 * DD; i += NTHR) {
            int n = i / DD, c = i % DD;
            Y[i] = (t[i] - sp->m[n]) * sp->rs[n] * n1_g[l * DD + c] + n1_b[l * DD + c];
        }
        for (int c = tid; c < DD; c += NTHR) Y[65 * DD + c] = 0.f;
        issue_qkv(0, 0);   // prefetch head-0 stage-0 (Y published by the s0 barrier)

        const float asc = attn_scale[l];
        const int cg = warp % 3, rg = warp / 3;     // 3 colgroups x 8 rowgroups
        const int row0 = rg * 9;
        const int colb = cg * 64 + lane;

        for (int h = 0; h < NHD; h++) {
            // ===== qkv GEMM head h: S[72x192], k=192, 8 stages x 6 k4 =====
            {
                ull acc[18];
#pragma unroll
                for (int i = 0; i < 18; i++) acc[i] = 0ull;
                for (int s = 0; s < 8; s++) {
                    cp_wait_all();
                    __syncthreads();
                    if (s < 7) issue_qkv(h, s + 1);
                    const float4* wb = Wsh4 + (s & 1) * HALF;
                    int k40 = s * 6;
#pragma unroll 2
                    for (int kk = 0; kk < 6; kk++) {
                        ulonglong2 w0 = *(const ulonglong2*)(wb + kk * PADQ + colb);
                        ulonglong2 w1 = *(const ulonglong2*)(wb + kk * PADQ + colb + 32);
#pragma unroll
                        for (int r = 0; r < 9; r++) {
                            ulonglong2 yv = *(const ulonglong2*)(Y + (row0 + r) * DD + 4 * (k40 + kk));
                            acc[r]     = fma2(yv.x, w0.x, acc[r]);     acc[r]     = fma2(yv.y, w0.y, acc[r]);
                            acc[9 + r] = fma2(yv.x, w1.x, acc[9 + r]); acc[9 + r] = fma2(yv.y, w1.y, acc[9 + r]);
                        }
                    }
                }
#pragma unroll
                for (int r = 0; r < 9; r++) {
                    S[(row0 + r) * DD + colb]      = f2sum(acc[r]);
                    S[(row0 + r) * DD + colb + 32] = f2sum(acc[9 + r]);
                }
            }
            issue_proj(h, 0);      // buf0 (qkv ended on buf1); hidden under attention
            __syncthreads();       // publish S

            // ===== banded attention (|i-j|<=3) -> Oh =====
            {
                float coef = 0.125f / temp[l * NHD + h];
                for (int i = warp; i < 65; i += NWARP) {
                    int jlo = (i - 3 < 0) ? 0 : i - 3;
                    int jhi = (i + 3 > 64) ? 64 : i + 3;
                    int cnt = jhi - jlo + 1;
                    float2 qv = *(const float2*)(S + i * DD + 2 * lane);
                    float sc[7];
#pragma unroll
                    for (int jj = 0; jj < 7; jj++) {
                        if (jj < cnt) {
                            float2 kv = *(const float2*)(S + (jlo + jj) * DD + 64 + 2 * lane);
                            float p = qv.x * kv.x + qv.y * kv.y;
#pragma unroll
                            for (int o = 16; o; o >>= 1) p += __shfl_xor_sync(0xffffffffu, p, o);
                            sc[jj] = p * coef;
                        }
                    }
                    float mx = sc[0];
#pragma unroll
                    for (int jj = 1; jj < 7; jj++) if (jj < cnt) mx = fmaxf(mx, sc[jj]);
                    float ssum = 0.f;
#pragma unroll
                    for (int jj = 0; jj < 7; jj++) if (jj < cnt) { sc[jj] = expf(sc[jj] - mx); ssum += sc[jj]; }
                    float inv = 1.0f / ssum;
                    float o0 = 0.f, o1 = 0.f;
#pragma unroll
                    for (int jj = 0; jj < 7; jj++) {
                        if (jj < cnt) {
                            float2 vv = *(const float2*)(S + (jlo + jj) * DD + 128 + 2 * lane);
                            o0 += sc[jj] * vv.x;
                            o1 += sc[jj] * vv.y;
                        }
                    }
                    Oh[i * OHS + 2 * lane]     = o0 * inv;
                    Oh[i * OHS + 2 * lane + 1] = o1 * inv;
                }
            }

            // ===== proj partial (k=64 of head h): 4 stages x 4 k4 =====
            {
                ull acc[18];
#pragma unroll
                for (int i = 0; i < 18; i++) acc[i] = 0ull;
                for (int s = 0; s < 4; s++) {
                    cp_wait_all();
                    __syncthreads();   // s==0 also publishes Oh
                    if (s < 3) issue_proj(h, s + 1);
                    else if (h < 2) issue_qkv(h + 1, 0);   // buf0; s3 computes on buf1
                    const float4* wb = Wsh4 + (s & 1) * HALF;
                    int k40 = s * 4;
#pragma unroll 2
                    for (int kk = 0; kk < 4; kk++) {
                        ulonglong2 w0 = *(const ulonglong2*)(wb + kk * PADQ + colb);
                        ulonglong2 w1 = *(const ulonglong2*)(wb + kk * PADQ + colb + 32);
#pragma unroll
                        for (int r = 0; r < 9; r++) {
                            ulonglong2 ov = *(const ulonglong2*)(Oh + (row0 + r) * OHS + 4 * (k40 + kk));
                            acc[r]     = fma2(ov.x, w0.x, acc[r]);     acc[r]     = fma2(ov.y, w0.y, acc[r]);
                            acc[9 + r] = fma2(ov.x, w1.x, acc[9 + r]); acc[9 + r] = fma2(ov.y, w1.y, acc[9 + r]);
                        }
                    }
                }
#pragma unroll
                for (int r = 0; r < 9; r++) {
                    int row = row0 + r;
                    if (row < 66) {
                        float a0 = f2sum(acc[r]), a1 = f2sum(acc[9 + r]);
                        if (h == 0) {
                            a0 += proj_b[l * DD + colb];
                            a1 += proj_b[l * DD + colb + 32];
                        }
                        t[row * DD + colb]      += asc * a0;
                        t[row * DD + colb + 32] += asc * a1;
                    }
                }
            }
            // next head's qkv s0 barrier doubles as the end-of-head barrier
        }
        __syncthreads();   // publish t for LN2

        // ---- LN2 -> Y ----
        ln_stats(t, 0, 65, sp->m, sp->rs);
        __syncthreads();
        for (int i = tid; i < 65 * DD; i += NTHR) {
            int n = i / DD, c = i % DD;
            Y[i] = (t[i] - sp->m[n]) * sp->rs[n] * n2_g[l * DD + c] + n2_b[l * DD + c];
        }
        for (int c = tid; c < DD; c += NTHR) Y[65 * DD + c] = 0.f;
        __syncthreads();

        // ---- gating ----
        for (int task = tid; task < NT * NE; task += NTHR) {
            int n = task >> 2, e = task & 3;
            const float* gw = gate_w + ((size_t)l * NE + e) * DD;
            float acc = gate_b[l * NE + e];
            for (int c = 0; c < DD; c += 4) {
                float4 y4 = *(const float4*)(Y + n * DD + c);
                float4 w4 = *(const float4*)(gw + c);
                acc += dot4(y4, w4);
            }
            sp->gl[n * NE + e] = acc;
        }
        __syncthreads();
        if (tid < NT) {
            float vv[4] = { sp->gl[tid * 4 + 0], sp->gl[tid * 4 + 1],
                            sp->gl[tid * 4 + 2], sp->gl[tid * 4 + 3] };
            int i0 = 0; float bmax = vv[0];
#pragma unroll
            for (int e = 1; e < 4; e++) if (vv[e] > bmax) { bmax = vv[e]; i0 = e; }
            int i1 = -1; float b2v = -1e30f;
#pragma unroll
            for (int e = 0; e < 4; e++) if (e != i0 && vv[e] > b2v) { b2v = vv[e]; i1 = e; }
            float w1 = expf(b2v - bmax);
            float inv = 1.0f / (1.0f + w1);
            sp->seli[tid * 2 + 0] = i0;
            sp->seli[tid * 2 + 1] = i1;
            sp->selw[tid * 2 + 0] = inv;
            sp->selw[tid * 2 + 1] = w1 * inv;
        }
        __syncthreads();
        if (tid == 0) {
            float msc = mlp_scale[l];
            int cnt[4] = { 0, 0, 0, 0 };
            for (int n = 0; n < NT; n++) {
                for (int sidx = 0; sidx < 2; sidx++) {
                    int e = sp->seli[n * 2 + sidx];
                    sp->elist[e * 80 + cnt[e]] = n;
                    sp->ewt[e * 80 + cnt[e]] = sp->selw[n * 2 + sidx] * msc;
                    cnt[e]++;
                }
            }
            for (int e = 0; e < 4; e++) {
                while (cnt[e] % CK != 0) {
                    sp->elist[e * 80 + cnt[e]] = 65;   // Y row 65 = 0
                    sp->ewt[e * 80 + cnt[e]] = 0.f;
                    cnt[e]++;
                }
                sp->ecnt[e] = cnt[e];
            }
        }
        __syncthreads();

        // ---- expert FFNs (40-row chunks, cp.async pipelined) ----
        float* Hc = S;   // 40 x 384, spills into Oh (dead during MoE)
        auto issue_g1 = [&](const float* w1b, int s) {
            float4* dst = Wsh4 + (s & 1) * HALF;
            int k40 = s * 3;
            for (int i = tid; i < 384 * 3; i += NTHR) {
                int col = i / 3, kk = i - col * 3;
                cp_async16(&dst[kk * PADG + col], w1b + (size_t)col * DD + 4 * (k40 + kk));
            }
            cp_commit();
        };
        auto issue_g2 = [&](const float* w2b, int s) {
            float4* dst = Wsh4 + (s & 1) * HALF;
            int k40 = s * 6;
            for (int i = tid; i < 192 * 6; i += NTHR) {
                int col = i / 6, kk = i - col * 6;
                cp_async16(&dst[kk * PADQ + col], w2b + (size_t)col * DH + 4 * (k40 + kk));
            }
            cp_commit();
        };

        for (int e = 0; e < NE; e++) {
            int nch = sp->ecnt[e] / CK;
            const float* w1b = e_w1 + (size_t)(l * NE + e) * DH * DD;
            const float* w2b = e_w2 + (size_t)(l * NE + e) * DD * DH;
            for (int ch = 0; ch < nch; ch++) {
                int base = e * 80 + ch * CK;

                // ===== G1: 40x384 = Y[toks] @ w1^T, k=192, 16 stages x 3 k4 =====
                {
                    const int cg1 = warp % 6, rg1 = warp / 6;   // 6 cg x 4 rg
                    const int r1 = rg1 * 10;
                    const int cb1 = cg1 * 64 + lane;
                    issue_g1(w1b, 0);   // buf0; prior Wsh use ended on buf1 or is bar-protected
                    int toks[10];
#pragma unroll
                    for (int r = 0; r < 10; r++) toks[r] = sp->elist[base + r1 + r];
                    ull acc[20];
#pragma unroll
                    for (int i = 0; i < 20; i++) acc[i] = 0ull;
                    for (int s = 0; s < 16; s++) {
                        cp_wait_all();
                        __syncthreads();
                        if (s < 15) issue_g1(w1b, s + 1);
                        else issue_g2(w2b, 0);   // buf0; s15 computes on buf1
                        const float4* wb = Wsh4 + (s & 1) * HALF;
                        int k40 = s * 3;
#pragma unroll
                        for (int kk = 0; kk < 3; kk++) {
                            ulonglong2 w0 = *(const ulonglong2*)(wb + kk * PADG + cb1);
                            ulonglong2 w1 = *(const ulonglong2*)(wb + kk * PADG + cb1 + 32);
#pragma unroll
                            for (int r = 0; r < 10; r++) {
                                ulonglong2 yv = *(const ulonglong2*)(Y + toks[r] * DD + 4 * (k40 + kk));
                                acc[r]      = fma2(yv.x, w0.x, acc[r]);      acc[r]      = fma2(yv.y, w0.y, acc[r]);
                                acc[10 + r] = fma2(yv.x, w1.x, acc[10 + r]); acc[10 + r] = fma2(yv.y, w1.y, acc[10 + r]);
                            }
                        }
                    }
                    const float* b1 = e_b1 + (size_t)(l * NE + e) * DH;
#pragma unroll
                    for (int r = 0; r < 10; r++) {
                        Hc[(r1 + r) * DH + cb1]      = gelu_exact(f2sum(acc[r]) + b1[cb1]);
                        Hc[(r1 + r) * DH + cb1 + 32] = gelu_exact(f2sum(acc[10 + r]) + b1[cb1 + 32]);
                    }
                }

                // ===== G2: 40x192 = Hc @ w2^T, k=384, 16 stages x 6 k4 =====
                {
                    const int cg2 = warp % 3, rg2 = warp / 3;   // 3 cg x 8 rg
                    const int r2 = rg2 * 5;
                    const int cb2 = cg2 * 64 + lane;
                    ull acc[10];
#pragma unroll
                    for (int i = 0; i < 10; i++) acc[i] = 0ull;
                    for (int s = 0; s < 16; s++) {
                        cp_wait_all();
                        __syncthreads();   // s==0 also publishes Hc
                        if (s < 15) issue_g2(w2b, s + 1);
                        const float4* wb = Wsh4 + (s & 1) * HALF;
                        int k40 = s * 6;
#pragma unroll 2
                        for (int kk = 0; kk < 6; kk++) {
                            ulonglong2 w0 = *(const ulonglong2*)(wb + kk * PADQ + cb2);
                            ulonglong2 w1 = *(const ulonglong2*)(wb + kk * PADQ + cb2 + 32);
#pragma unroll
                            for (int r = 0; r < 5; r++) {
                                ulonglong2 hv = *(const ulonglong2*)(Hc + (r2 + r) * DH + 4 * (k40 + kk));
                                acc[r]     = fma2(hv.x, w0.x, acc[r]);     acc[r]     = fma2(hv.y, w0.y, acc[r]);
                                acc[5 + r] = fma2(hv.x, w1.x, acc[5 + r]); acc[5 + r] = fma2(hv.y, w1.y, acc[5 + r]);
                            }
                        }
                    }
                    const float* b2 = e_b2 + (size_t)(l * NE + e) * DD;
#pragma unroll
                    for (int r = 0; r < 5; r++) {
                        int tok = sp->elist[base + r2 + r];
                        float wt = sp->ewt[base + r2 + r];
                        t[tok * DD + cb2]      += wt * (f2sum(acc[r]) + b2[cb2]);
                        t[tok * DD + cb2 + 32] += wt * (f2sum(acc[5 + r]) + b2[cb2 + 32]);
                    }
                }
                // next chunk's G1-s0 barrier protects Wsh and orders t-scatters
            }
        }
        __syncthreads();   // publish t for next layer / final norm
    }

    // ======================= final norm + circulant head =======================
    ln_stats(t, 0, 1, sp->m, sp->rs);
    __syncthreads();
    float* cls = Y;
    for (int c = tid; c < DD; c += NTHR)
        cls[c] = (t[c] - sp->m[0]) * sp->rs[0] * norm_g[c] + norm_b[c];
    __syncthreads();
    float* HH = S;
    for (int ko = tid; ko < 2 * DD; ko += NTHR) {
        int k = ko / 96, o = ko % 96;
        float acc = hc_b[ko];
#pragma unroll
        for (int j = 0; j < 4; j++) {
            const float* w = hc_w + ((size_t)((k - j) & 3) * 96 + o) * 48;
            const float* xv = cls + j * 48;
#pragma unroll
            for (int c = 0; c < 48; c += 4) {
                float4 w4 = *(const float4*)(w + c);
                float4 x4 = *(const float4*)(xv + c);
                acc += dot4(x4, w4);
            }
        }
        HH[ko] = gelu_exact(acc);
    }
    __syncthreads();
    for (int ci = tid; ci < NCLS; ci += NTHR) {
        const float* w = head_w + (size_t)ci * (2 * DD);
        float acc = head_b[ci];
        for (int c = 0; c < 2 * DD; c += 4) {
            float4 w4 = *(const float4*)(w + c);
            float4 h4 = *(const float4*)(HH + c);
            acc += dot4(h4, w4);
        }
        out[b * NCLS + ci] = acc;
    }
}

extern "C" void kernel_launch(void* const* d_in, const int* in_sizes, int n_in,
                              void* d_out, int out_size) {
    (void)in_sizes; (void)n_in; (void)out_size;
    const float* x          = (const float*)d_in[0];
    const float* conv_w     = (const float*)d_in[1];
    const float* conv_b     = (const float*)d_in[2];
    const float* pe_g       = (const float*)d_in[3];
    const float* pe_b       = (const float*)d_in[4];
    const float* cls_token  = (const float*)d_in[5];
    const float* pos_embed  = (const float*)d_in[6];
    const float* n1_g       = (const float*)d_in[7];
    const float* n1_b       = (const float*)d_in[8];
    const float* qkv_w      = (const float*)d_in[9];
    const float* temp       = (const float*)d_in[10];
    const float* proj_w     = (const float*)d_in[11];
    const float* proj_b     = (const float*)d_in[12];
    const float* n2_g       = (const float*)d_in[13];
    const float* n2_b       = (const float*)d_in[14];
    const float* gate_w     = (const float*)d_in[15];
    const float* gate_b     = (const float*)d_in[16];
    const float* e_w1       = (const float*)d_in[17];
    const float* e_b1       = (const float*)d_in[18];
    const float* e_w2       = (const float*)d_in[19];
    const float* e_b2       = (const float*)d_in[20];
    const float* attn_scale = (const float*)d_in[21];
    const float* mlp_scale  = (const float*)d_in[22];
    const float* norm_g     = (const float*)d_in[23];
    const float* norm_b     = (const float*)d_in[24];
    const float* hc_w       = (const float*)d_in[25];
    const float* hc_b       = (const float*)d_in[26];
    const float* head_w     = (const float*)d_in[27];
    const float* head_b     = (const float*)d_in[28];

    cudaFuncSetAttribute(hypervit_kernel, cudaFuncAttributeMaxDynamicSharedMemorySize,
                         (int)sizeof(SM));
    hypervit_kernel<<<NB, NTHR, sizeof(SM)>>>(
        x, conv_w, conv_b, pe_g, pe_b, cls_token, pos_embed,
        n1_g, n1_b, qkv_w, temp, proj_w, proj_b, n2_g, n2_b,
        gate_w, gate_b, e_w1, e_b1, e_w2, e_b2,
        attn_scale, mlp_scale, norm_g, norm_b, hc_w, hc_b,
        head_w, head_b, (float*)d_out);
}

// round 12
// speedup vs baseline: 1.4614x; 1.4614x over previous
#include <cuda_runtime.h>
#include <math.h>

#define NB 128
#define DD 192
#define DEPTHL 12
#define NHD 3
#define HDIM 64
#define NE 4
#define NT 65
#define NCLS 100
#define DH 384
#define NTHR 768
#define NWARP 24
#define YS 196          // padded Y row stride (= 4 mod 32 -> conflict-free mma a-frags)
#define HTS 196         // Htf row stride
#define OHS 68
#define PADQ 193
#define WBUF 2316       // 12*193 float4 (qkv/proj staging only)

typedef unsigned long long ull;

struct __align__(16) SM {
    float t[66 * DD];
    float Y[72 * YS];        // fp32 LN output; becomes tf32 bits during MoE
    float S[72 * DD];        // qkv per head; MoE: Htf (48 x HTS u32) aliases
    float Oh[72 * OHS];
    float4 Wsh4[WBUF];
    float m[72], rs[72];
    float gl[NT * NE];
    float selw[NT * 2];
    float ewt[NE * 80];
    int   seli[NT * 2];
    int   elist[NE * 80];
    int   ecnt[NE];
};

__device__ __forceinline__ ull fma2(ull a, ull b, ull c) {
    ull d;
    asm("fma.rn.f32x2 %0, %1, %2, %3;" : "=l"(d) : "l"(a), "l"(b), "l"(c));
    return d;
}
__device__ __forceinline__ float f2sum(ull v) {
    float lo = __uint_as_float((unsigned)(v & 0xffffffffull));
    float hi = __uint_as_float((unsigned)(v >> 32));
    return lo + hi;
}
__device__ __forceinline__ float gelu_exact(float x) {
    return 0.5f * x * (1.0f + erff(x * 0.70710678118654752f));
}
__device__ __forceinline__ float dot4(float4 a, float4 b) {
    return a.x * b.x + a.y * b.y + a.z * b.z + a.w * b.w;
}
__device__ __forceinline__ unsigned to_tf32(float f) {
    unsigned u;
    asm("cvt.rna.tf32.f32 %0, %1;" : "=r"(u) : "f"(f));
    return u;
}
__device__ __forceinline__ void mma_tf32(float* c, unsigned a0, unsigned a1, unsigned a2, unsigned a3,
                                         unsigned b0, unsigned b1) {
    asm volatile(
        "mma.sync.aligned.m16n8k8.row.col.f32.tf32.tf32.f32 "
        "{%0,%1,%2,%3},{%4,%5,%6,%7},{%8,%9},{%0,%1,%2,%3};"
        : "+f"(c[0]), "+f"(c[1]), "+f"(c[2]), "+f"(c[3])
        : "r"(a0), "r"(a1), "r"(a2), "r"(a3), "r"(b0), "r"(b1));
}

__device__ __forceinline__ void ln_stats(const float* __restrict__ base, int n0, int n1,
                                         float* __restrict__ m, float* __restrict__ rs) {
    int warp = threadIdx.x >> 5, lane = threadIdx.x & 31;
    for (int n = n0 + warp; n < n1; n += NWARP) {
        const float* row = base + n * DD;
        float s = 0.f;
        for (int c = lane; c < DD; c += 32) s += row[c];
#pragma unroll
        for (int o = 16; o; o >>= 1) s += __shfl_xor_sync(0xffffffffu, s, o);
        float mm = s * (1.0f / DD);
        float q = 0.f;
        for (int c = lane; c < DD; c += 32) { float d = row[c] - mm; q += d * d; }
#pragma unroll
        for (int o = 16; o; o >>= 1) q += __shfl_xor_sync(0xffffffffu, q, o);
        if (lane == 0) { m[n] = mm; rs[n] = rsqrtf(q * (1.0f / DD) + 1e-5f); }
    }
}

__global__ void __launch_bounds__(NTHR, 1) hypervit_kernel(
    const float* __restrict__ x, const float* __restrict__ conv_w, const float* __restrict__ conv_b,
    const float* __restrict__ pe_g, const float* __restrict__ pe_b,
    const float* __restrict__ cls_token, const float* __restrict__ pos_embed,
    const float* __restrict__ n1_g, const float* __restrict__ n1_b,
    const float* __restrict__ qkv_w, const float* __restrict__ temp,
    const float* __restrict__ proj_w, const float* __restrict__ proj_b,
    const float* __restrict__ n2_g, const float* __restrict__ n2_b,
    const float* __restrict__ gate_w, const float* __restrict__ gate_b,
    const float* __restrict__ e_w1, const float* __restrict__ e_b1,
    const float* __restrict__ e_w2, const float* __restrict__ e_b2,
    const float* __restrict__ attn_scale, const float* __restrict__ mlp_scale,
    const float* __restrict__ norm_g, const float* __restrict__ norm_b,
    const float* __restrict__ hc_w, const float* __restrict__ hc_b,
    const float* __restrict__ head_w, const float* __restrict__ head_b,
    float* __restrict__ out)
{
    extern __shared__ char smraw[];
    SM* sp = (SM*)smraw;
    const int b = blockIdx.x;
    const int tid = threadIdx.x;
    const int warp = tid >> 5, lane = tid & 31;
    const int l4 = lane & 3, lq = lane >> 2;
    float* t = sp->t;
    float* Y = sp->Y;
    float* S = sp->S;
    float* Oh = sp->Oh;
    float4* Wsh4 = sp->Wsh4;

    for (int i = tid; i < 6 * YS; i += NTHR) Y[66 * YS + i] = 0.f;

    // ======================= patch embed =======================
    {
        float* P = Y;
        for (int i = tid; i < 64 * 48; i += NTHR) {
            int patch = i / 48, f = i % 48;
            int c = f >> 4, pi = (f >> 2) & 3, pj = f & 3;
            int ph = patch >> 3, pw = patch & 7;
            P[i] = x[((b * 3 + c) * 32 + ph * 4 + pi) * 32 + pw * 4 + pj];
        }
        __syncthreads();
        for (int task = tid; task < 64 * DD; task += NTHR) {
            int p = task / DD, c = task % DD;
            const float* w = conv_w + c * 48;
            float acc = conv_b[c];
#pragma unroll
            for (int k = 0; k < 48; k += 4) {
                float4 w4 = *(const float4*)(w + k);
                float4 p4 = *(const float4*)(P + p * 48 + k);
                acc += dot4(p4, w4);
            }
            t[(p + 1) * DD + c] = acc;
        }
        __syncthreads();
        ln_stats(t, 1, 65, sp->m, sp->rs);
        __syncthreads();
        for (int i = tid; i < 64 * DD; i += NTHR) {
            int n = 1 + i / DD, c = i % DD;
            t[n * DD + c] = (t[n * DD + c] - sp->m[n]) * sp->rs[n] * pe_g[c] + pe_b[c]
                            + pos_embed[n * DD + c];
        }
        for (int c = tid; c < DD; c += NTHR) {
            t[c] = cls_token[c] + pos_embed[c];
            t[65 * DD + c] = 0.f;
        }
    }
    __syncthreads();

    // ======================= transformer layers =======================
    for (int l = 0; l < DEPTHL; l++) {
        // ---- LN1 -> Y ----
        ln_stats(t, 0, 65, sp->m, sp->rs);
        __syncthreads();
        for (int i = tid; i < 65 * DD; i += NTHR) {
            int n = i / DD, c = i % DD;
            Y[n * YS + c] = (t[i] - sp->m[n]) * sp->rs[n] * n1_g[l * DD + c] + n1_b[l * DD + c];
        }
        for (int c = tid; c < DD; c += NTHR) Y[65 * YS + c] = 0.f;
        // first staging barrier publishes Y

        const float asc = attn_scale[l];
        const int cg = warp % 3, rg = warp / 3;     // 3 colgroups x 8 rowgroups
        const int row0 = rg * 9;
        const int colb = cg * 64 + lane;

        for (int h = 0; h < NHD; h++) {
            // ===== qkv GEMM head h: S[72x192], k=192, 4 stages x 12 k4 =====
            {
                ull acc[18];
#pragma unroll
                for (int i = 0; i < 18; i++) acc[i] = 0ull;
                for (int s = 0; s < 4; s++) {
                    int k40 = s * 12;
                    __syncthreads();
                    for (int i = tid; i < 192 * 12; i += NTHR) {
                        int col = i / 12, kk = i - col * 12;
                        int sec = col >> 6, d = col & 63;
                        const float* src = qkv_w + ((size_t)(l * 3 + sec) * DD + h * HDIM + d) * DD
                                           + 4 * (k40 + kk);
                        Wsh4[kk * PADQ + col] = *(const float4*)src;
                    }
                    __syncthreads();
#pragma unroll 3
                    for (int kk = 0; kk < 12; kk++) {
                        ulonglong2 w0 = *(const ulonglong2*)(Wsh4 + kk * PADQ + colb);
                        ulonglong2 w1 = *(const ulonglong2*)(Wsh4 + kk * PADQ + colb + 32);
#pragma unroll
                        for (int r = 0; r < 9; r++) {
                            ulonglong2 yv = *(const ulonglong2*)(Y + (row0 + r) * YS + 4 * (k40 + kk));
                            acc[r]     = fma2(yv.x, w0.x, acc[r]);     acc[r]     = fma2(yv.y, w0.y, acc[r]);
                            acc[9 + r] = fma2(yv.x, w1.x, acc[9 + r]); acc[9 + r] = fma2(yv.y, w1.y, acc[9 + r]);
                        }
                    }
                }
#pragma unroll
                for (int r = 0; r < 9; r++) {
                    S[(row0 + r) * DD + colb]      = f2sum(acc[r]);
                    S[(row0 + r) * DD + colb + 32] = f2sum(acc[9 + r]);
                }
            }
            __syncthreads();

            // ===== banded attention (|i-j|<=3) -> Oh =====
            {
                float coef = 0.125f / temp[l * NHD + h];
                for (int i = warp; i < 65; i += NWARP) {
                    int jlo = (i - 3 < 0) ? 0 : i - 3;
                    int jhi = (i + 3 > 64) ? 64 : i + 3;
                    int cnt = jhi - jlo + 1;
                    float2 qv = *(const float2*)(S + i * DD + 2 * lane);
                    float sc[7];
#pragma unroll
                    for (int jj = 0; jj < 7; jj++) {
                        if (jj < cnt) {
                            float2 kv = *(const float2*)(S + (jlo + jj) * DD + 64 + 2 * lane);
                            float p = qv.x * kv.x + qv.y * kv.y;
#pragma unroll
                            for (int o = 16; o; o >>= 1) p += __shfl_xor_sync(0xffffffffu, p, o);
                            sc[jj] = p * coef;
                        }
                    }
                    float mx = sc[0];
#pragma unroll
                    for (int jj = 1; jj < 7; jj++) if (jj < cnt) mx = fmaxf(mx, sc[jj]);
                    float ssum = 0.f;
#pragma unroll
                    for (int jj = 0; jj < 7; jj++) if (jj < cnt) { sc[jj] = expf(sc[jj] - mx); ssum += sc[jj]; }
                    float inv = 1.0f / ssum;
                    float o0 = 0.f, o1 = 0.f;
#pragma unroll
                    for (int jj = 0; jj < 7; jj++) {
                        if (jj < cnt) {
                            float2 vv = *(const float2*)(S + (jlo + jj) * DD + 128 + 2 * lane);
                            o0 += sc[jj] * vv.x;
                            o1 += sc[jj] * vv.y;
                        }
                    }
                    Oh[i * OHS + 2 * lane]     = o0 * inv;
                    Oh[i * OHS + 2 * lane + 1] = o1 * inv;
                }
            }

            // ===== proj partial (k=64 of head h): 2 stages of 8 k4 =====
            {
                ull acc[18];
#pragma unroll
                for (int i = 0; i < 18; i++) acc[i] = 0ull;
                for (int s = 0; s < 2; s++) {
                    int k40 = s * 8;
                    __syncthreads();   // s==0 also publishes Oh
                    for (int i = tid; i < 192 * 8; i += NTHR) {
                        int col = i / 8, kk = i - col * 8;
                        const float* src = proj_w + ((size_t)l * DD + col) * DD + h * HDIM + 4 * (k40 + kk);
                        Wsh4[kk * PADQ + col] = *(const float4*)src;
                    }
                    __syncthreads();
#pragma unroll 2
                    for (int kk = 0; kk < 8; kk++) {
                        ulonglong2 w0 = *(const ulonglong2*)(Wsh4 + kk * PADQ + colb);
                        ulonglong2 w1 = *(const ulonglong2*)(Wsh4 + kk * PADQ + colb + 32);
#pragma unroll
                        for (int r = 0; r < 9; r++) {
                            ulonglong2 ov = *(const ulonglong2*)(Oh + (row0 + r) * OHS + 4 * (k40 + kk));
                            acc[r]     = fma2(ov.x, w0.x, acc[r]);     acc[r]     = fma2(ov.y, w0.y, acc[r]);
                            acc[9 + r] = fma2(ov.x, w1.x, acc[9 + r]); acc[9 + r] = fma2(ov.y, w1.y, acc[9 + r]);
                        }
                    }
                }
#pragma unroll
                for (int r = 0; r < 9; r++) {
                    int row = row0 + r;
                    if (row < 66) {
                        float a0 = f2sum(acc[r]), a1 = f2sum(acc[9 + r]);
                        if (h == 0) {
                            a0 += proj_b[l * DD + colb];
                            a1 += proj_b[l * DD + colb + 32];
                        }
                        t[row * DD + colb]      += asc * a0;
                        t[row * DD + colb + 32] += asc * a1;
                    }
                }
            }
            __syncthreads();
        }

        // ---- LN2 -> Y ----
        ln_stats(t, 0, 65, sp->m, sp->rs);
        __syncthreads();
        for (int i = tid; i < 65 * DD; i += NTHR) {
            int n = i / DD, c = i % DD;
            Y[n * YS + c] = (t[i] - sp->m[n]) * sp->rs[n] * n2_g[l * DD + c] + n2_b[l * DD + c];
        }
        for (int c = tid; c < DD; c += NTHR) Y[65 * YS + c] = 0.f;
        __syncthreads();

        // ---- gating (reads fp32 Y) ----
        for (int task = tid; task < NT * NE; task += NTHR) {
            int n = task >> 2, e = task & 3;
            const float* gw = gate_w + ((size_t)l * NE + e) * DD;
            float acc = gate_b[l * NE + e];
            for (int c = 0; c < DD; c += 4) {
                float4 y4 = *(const float4*)(Y + n * YS + c);
                float4 w4 = *(const float4*)(gw + c);
                acc += dot4(y4, w4);
            }
            sp->gl[n * NE + e] = acc;
        }
        __syncthreads();
        // convert Y rows 0..65 in place to tf32 (gating done); top-2 select in parallel
        for (int i = tid; i < 66 * DD; i += NTHR) {
            int n = i / DD, c = i % DD;
            ((unsigned*)Y)[n * YS + c] = to_tf32(Y[n * YS + c]);
        }
        if (tid < NT) {
            float vv[4] = { sp->gl[tid * 4 + 0], sp->gl[tid * 4 + 1],
                            sp->gl[tid * 4 + 2], sp->gl[tid * 4 + 3] };
            int i0 = 0; float bmax = vv[0];
#pragma unroll
            for (int e = 1; e < 4; e++) if (vv[e] > bmax) { bmax = vv[e]; i0 = e; }
            int i1 = -1; float b2v = -1e30f;
#pragma unroll
            for (int e = 0; e < 4; e++) if (e != i0 && vv[e] > b2v) { b2v = vv[e]; i1 = e; }
            float w1 = expf(b2v - bmax);
            float inv = 1.0f / (1.0f + w1);
            sp->seli[tid * 2 + 0] = i0;
            sp->seli[tid * 2 + 1] = i1;
            sp->selw[tid * 2 + 0] = inv;
            sp->selw[tid * 2 + 1] = w1 * inv;
        }
        __syncthreads();
        if (tid == 0) {
            float msc = mlp_scale[l];
            int cnt[4] = { 0, 0, 0, 0 };
            for (int n = 0; n < NT; n++) {
                for (int sidx = 0; sidx < 2; sidx++) {
                    int e = sp->seli[n * 2 + sidx];
                    sp->elist[e * 80 + cnt[e]] = n;
                    sp->ewt[e * 80 + cnt[e]] = sp->selw[n * 2 + sidx] * msc;
                    cnt[e]++;
                }
            }
            for (int e = 0; e < 4; e++) {
                while (cnt[e] % 16 != 0) {
                    sp->elist[e * 80 + cnt[e]] = 65;   // tf32 zero row
                    sp->ewt[e * 80 + cnt[e]] = 0.f;
                    cnt[e]++;
                }
                sp->ecnt[e] = cnt[e];
            }
        }
        __syncthreads();

        // ---- expert FFNs on tensor cores (tf32 mma), per expert, 48-row blocks ----
        const unsigned* YT = (const unsigned*)Y;
        unsigned* Htf = (unsigned*)S;     // 48 x HTS (S dead during MoE)
        for (int e = 0; e < NE; e++) {
            int cnt = sp->ecnt[e];
            if (cnt == 0) continue;
            const float* w1b = e_w1 + (size_t)(l * NE + e) * DH * DD;
            const float* w2b = e_w2 + (size_t)(l * NE + e) * DD * DH;
            const float* b1p = e_b1 + (size_t)(l * NE + e) * DH;
            const float* b2p = e_b2 + (size_t)(l * NE + e) * DD;
            int base0 = e * 80;
            for (int mb = 0; mb < cnt; mb += 48) {
                int nmt = (cnt - mb) >> 4; if (nmt > 3) nmt = 3;
                int tokA[3], tokB[3];
#pragma unroll
                for (int mt = 0; mt < 3; mt++) if (mt < nmt) {
                    tokA[mt] = sp->elist[base0 + mb + mt * 16 + lq];
                    tokB[mt] = sp->elist[base0 + mb + mt * 16 + 8 + lq];
                }
                float acc2[3][4];
#pragma unroll
                for (int mt = 0; mt < 3; mt++)
#pragma unroll
                    for (int i = 0; i < 4; i++) acc2[mt][i] = 0.f;

                for (int kh = 0; kh < 2; kh++) {
                    // ===== G1: H[:, kh*192..] = Y @ w1^T (this N-half), K=192 =====
                    float acc1[3][4];
#pragma unroll
                    for (int mt = 0; mt < 3; mt++)
#pragma unroll
                        for (int i = 0; i < 4; i++) acc1[mt][i] = 0.f;
                    {
                        const float* wb = w1b + (size_t)(kh * 192 + warp * 8 + lq) * DD + l4;
                        float pb0 = wb[0], pb1 = wb[4];
#pragma unroll 2
                        for (int ks = 0; ks < 24; ks++) {
                            float nb0 = 0.f, nb1 = 0.f;
                            if (ks < 23) { nb0 = wb[(ks + 1) * 8]; nb1 = wb[(ks + 1) * 8 + 4]; }
                            unsigned ub0 = to_tf32(pb0), ub1 = to_tf32(pb1);
                            int k0 = ks * 8 + l4;
#pragma unroll
                            for (int mt = 0; mt < 3; mt++) if (mt < nmt) {
                                unsigned a0 = YT[tokA[mt] * YS + k0];
                                unsigned a1 = YT[tokB[mt] * YS + k0];
                                unsigned a2 = YT[tokA[mt] * YS + k0 + 4];
                                unsigned a3 = YT[tokB[mt] * YS + k0 + 4];
                                mma_tf32(acc1[mt], a0, a1, a2, a3, ub0, ub1);
                            }
                            pb0 = nb0; pb1 = nb1;
                        }
                    }
                    // G1 epilogue: bias + gelu -> tf32 H
                    {
                        int cl = warp * 8 + 2 * l4;
                        float bia0 = b1p[kh * 192 + cl], bia1 = b1p[kh * 192 + cl + 1];
#pragma unroll
                        for (int mt = 0; mt < 3; mt++) if (mt < nmt) {
                            int rA = mt * 16 + lq, rB = rA + 8;
                            Htf[rA * HTS + cl]     = to_tf32(gelu_exact(acc1[mt][0] + bia0));
                            Htf[rA * HTS + cl + 1] = to_tf32(gelu_exact(acc1[mt][1] + bia1));
                            Htf[rB * HTS + cl]     = to_tf32(gelu_exact(acc1[mt][2] + bia0));
                            Htf[rB * HTS + cl + 1] = to_tf32(gelu_exact(acc1[mt][3] + bia1));
                        }
                    }
                    __syncthreads();   // publish Htf
                    // ===== G2 partial: acc2 += H_half @ w2^T (K=192 of this half) =====
                    {
                        const float* wb = w2b + (size_t)(warp * 8 + lq) * DH + kh * 192 + l4;
                        float pb0 = wb[0], pb1 = wb[4];
#pragma unroll 2
                        for (int ks = 0; ks < 24; ks++) {
                            float nb0 = 0.f, nb1 = 0.f;
                            if (ks < 23) { nb0 = wb[(ks + 1) * 8]; nb1 = wb[(ks + 1) * 8 + 4]; }
                            unsigned ub0 = to_tf32(pb0), ub1 = to_tf32(pb1);
                            int k0 = ks * 8 + l4;
#pragma unroll
                            for (int mt = 0; mt < 3; mt++) if (mt < nmt) {
                                unsigned a0 = Htf[(mt * 16 + lq) * HTS + k0];
                                unsigned a1 = Htf[(mt * 16 + 8 + lq) * HTS + k0];
                                unsigned a2 = Htf[(mt * 16 + lq) * HTS + k0 + 4];
                                unsigned a3 = Htf[(mt * 16 + 8 + lq) * HTS + k0 + 4];
                                mma_tf32(acc2[mt], a0, a1, a2, a3, ub0, ub1);
                            }
                            pb0 = nb0; pb1 = nb1;
                        }
                    }
                    __syncthreads();   // Htf consumed before next kh overwrites
                }
                // G2 epilogue: scatter += into residual t
                {
                    int c = warp * 8 + 2 * l4;
                    float bb0 = b2p[c], bb1 = b2p[c + 1];
#pragma unroll
                    for (int mt = 0; mt < 3; mt++) if (mt < nmt) {
                        int iA = base0 + mb + mt * 16 + lq, iB = iA + 8;
                        int tA = sp->elist[iA]; float wA = sp->ewt[iA];
                        int tB = sp->elist[iB]; float wB = sp->ewt[iB];
                        t[tA * DD + c]     += wA * (acc2[mt][0] + bb0);
                        t[tA * DD + c + 1] += wA * (acc2[mt][1] + bb1);
                        t[tB * DD + c]     += wB * (acc2[mt][2] + bb0);
                        t[tB * DD + c + 1] += wB * (acc2[mt][3] + bb1);
                    }
                }
                __syncthreads();
            }
        }
        __syncthreads();   // publish t for next layer / final norm
    }

    // ======================= final norm + circulant head =======================
    ln_stats(t, 0, 1, sp->m, sp->rs);
    __syncthreads();
    float* cls = Y;
    for (int c = tid; c < DD; c += NTHR)
        cls[c] = (t[c] - sp->m[0]) * sp->rs[0] * norm_g[c] + norm_b[c];
    __syncthreads();
    float* HH = S;
    for (int ko = tid; ko < 2 * DD; ko += NTHR) {
        int k = ko / 96, o = ko % 96;
        float acc = hc_b[ko];
#pragma unroll
        for (int j = 0; j < 4; j++) {
            const float* w = hc_w + ((size_t)((k - j) & 3) * 96 + o) * 48;
            const float* xv = cls + j * 48;
#pragma unroll
            for (int c = 0; c < 48; c += 4) {
                float4 w4 = *(const float4*)(w + c);
                float4 x4 = *(const float4*)(xv + c);
                acc += dot4(x4, w4);
            }
        }
        HH[ko] = gelu_exact(acc);
    }
    __syncthreads();
    for (int ci = tid; ci < NCLS; ci += NTHR) {
        const float* w = head_w + (size_t)ci * (2 * DD);
        float acc = head_b[ci];
        for (int c = 0; c < 2 * DD; c += 4) {
            float4 w4 = *(const float4*)(w + c);
            float4 h4 = *(const float4*)(HH + c);
            acc += dot4(h4, w4);
        }
        out[b * NCLS + ci] = acc;
    }
}

extern "C" void kernel_launch(void* const* d_in, const int* in_sizes, int n_in,
                              void* d_out, int out_size) {
    (void)in_sizes; (void)n_in; (void)out_size;
    const float* x          = (const float*)d_in[0];
    const float* conv_w     = (const float*)d_in[1];
    const float* conv_b     = (const float*)d_in[2];
    const float* pe_g       = (const float*)d_in[3];
    const float* pe_b       = (const float*)d_in[4];
    const float* cls_token  = (const float*)d_in[5];
    const float* pos_embed  = (const float*)d_in[6];
    const float* n1_g       = (const float*)d_in[7];
    const float* n1_b       = (const float*)d_in[8];
    const float* qkv_w      = (const float*)d_in[9];
    const float* temp       = (const float*)d_in[10];
    const float* proj_w     = (const float*)d_in[11];
    const float* proj_b     = (const float*)d_in[12];
    const float* n2_g       = (const float*)d_in[13];
    const float* n2_b       = (const float*)d_in[14];
    const float* gate_w     = (const float*)d_in[15];
    const float* gate_b     = (const float*)d_in[16];
    const float* e_w1       = (const float*)d_in[17];
    const float* e_b1       = (const float*)d_in[18];
    const float* e_w2       = (const float*)d_in[19];
    const float* e_b2       = (const float*)d_in[20];
    const float* attn_scale = (const float*)d_in[21];
    const float* mlp_scale  = (const float*)d_in[22];
    const float* norm_g     = (const float*)d_in[23];
    const float* norm_b     = (const float*)d_in[24];
    const float* hc_w       = (const float*)d_in[25];
    const float* hc_b       = (const float*)d_in[26];
    const float* head_w     = (const float*)d_in[27];
    const float* head_b     = (const float*)d_in[28];

    cudaFuncSetAttribute(hypervit_kernel, cudaFuncAttributeMaxDynamicSharedMemorySize,
                         (int)sizeof(SM));
    hypervit_kernel<<<NB, NTHR, sizeof(SM)>>>(
        x, conv_w, conv_b, pe_g, pe_b, cls_token, pos_embed,
        n1_g, n1_b, qkv_w, temp, proj_w, proj_b, n2_g, n2_b,
        gate_w, gate_b, e_w1, e_b1, e_w2, e_b2,
        attn_scale, mlp_scale, norm_g, norm_b, hc_w, hc_b,
        head_w, head_b, (float*)d_out);
}